// round 12
// baseline (speedup 1.0000x reference)
#include <cuda_runtime.h>
#include <cstdint>

// Octree parent occupancy replicating the reference AS-EXECUTED under JAX
// default int32 (key arithmetic wraps mod 2^32 = 256*2^24):
//   - parent key folds px -> s = px mod 256, signed rep s-256 for s>=128
//   - unique/sort over folded keys; valid = (wrapped key >= 0) <=> s < 128
//   - valid rows decode to (s, py, pz); invalid rows -> (-1,-1,-1), occ=0
//   - leaf keys fold x mod 256; child query matches x = 2s+i (mod 256)
// Ordered parent index: P' = (s XOR 128)<<18 | py<<9 | pz  (ascending == ref order)
// Output layout: [ parent_C: N x 3 floats | occupancy: N x 8 floats ]

#define LEAF_WORDS (1u << 23)   // 2^28 bits (x mod 256, y, z) = 32 MiB
#define PAR_WORDS  (1u << 21)   // 2^26 bits = 8 MiB
#define NBLK       2048
#define WPB        1024         // NBLK*WPB == PAR_WORDS
#define PLIST_CAP  (1u << 22)

__device__ __align__(16) unsigned g_leafbm[LEAF_WORDS];
__device__ __align__(16) unsigned g_parbm[PAR_WORDS];
__device__ __align__(16) unsigned g_bsum[NBLK];
__device__ __align__(16) unsigned g_boff[NBLK];
__device__ __align__(16) unsigned g_plist[PLIST_CAP];
__device__ unsigned g_total;

// ---------------------------------------------------------------- scatter ---
__global__ void scatter_kernel(const float* __restrict__ leaf, int n) {
    int i = blockIdx.x * blockDim.x + threadIdx.x;
    if (i >= n) return;
    unsigned x = ((unsigned)(int)leaf[3 * i + 0]) & 1023u;
    unsigned y = ((unsigned)(int)leaf[3 * i + 1]) & 1023u;
    unsigned z = ((unsigned)(int)leaf[3 * i + 2]) & 1023u;
    unsigned L = ((x & 255u) << 20) | (y << 10) | z;      // folded leaf key
    atomicOr(&g_leafbm[L >> 5], 1u << (L & 31));
    unsigned s  = (x >> 1) & 255u;                        // px mod 256
    unsigned Pp = ((s ^ 128u) << 18) | ((y >> 1) << 9) | (z >> 1);
    atomicOr(&g_parbm[Pp >> 5], 1u << (Pp & 31));         // unconditional (fold!)
}

// --------------------------------------------------------- per-block sums ---
__global__ void blocksum_kernel() {
    unsigned t = threadIdx.x, b = blockIdx.x;
    const uint4* p = (const uint4*)g_parbm;
    uint4 w = p[(size_t)b * (WPB / 4) + t];
    unsigned c = __popc(w.x) + __popc(w.y) + __popc(w.z) + __popc(w.w);
    unsigned lane = t & 31, wid = t >> 5;
    #pragma unroll
    for (int d = 16; d; d >>= 1) c += __shfl_down_sync(0xffffffffu, c, d);
    __shared__ unsigned ws[8];
    if (lane == 0) ws[wid] = c;
    __syncthreads();
    if (t == 0) {
        unsigned s = 0;
        #pragma unroll
        for (int i = 0; i < 8; i++) s += ws[i];
        g_bsum[b] = s;
    }
}

// ------------------------------------------------ scan of 2048 block sums ---
__global__ void scan_kernel() {
    unsigned t = threadIdx.x;                       // 512 threads x 4 sums
    uint4 v = ((const uint4*)g_bsum)[t];
    unsigned s0 = v.x, s1 = v.y, s2 = v.z, s3 = v.w;
    unsigned tot = s0 + s1 + s2 + s3;
    unsigned lane = t & 31, wid = t >> 5;
    unsigned inc = tot;
    #pragma unroll
    for (int d = 1; d < 32; d <<= 1) {
        unsigned u = __shfl_up_sync(0xffffffffu, inc, d);
        if (lane >= d) inc += u;
    }
    __shared__ unsigned ws[16];
    if (lane == 31) ws[wid] = inc;
    __syncthreads();
    if (t == 0) {
        unsigned s = 0;
        #pragma unroll
        for (int i = 0; i < 16; i++) { unsigned x = ws[i]; ws[i] = s; s += x; }
        g_total = s;                                // Np' (unique folded keys)
    }
    __syncthreads();
    unsigned ex = ws[wid] + inc - tot;
    uint4 o;
    o.x = ex; o.y = ex + s0; o.z = ex + s0 + s1; o.w = ex + s0 + s1 + s2;
    ((uint4*)g_boff)[t] = o;
}

// ---------------------------------- ordered compaction: folded parent keys --
__global__ void compact_kernel() {
    unsigned t = threadIdx.x, b = blockIdx.x;
    unsigned widx0 = (b * 256u + t) * 4u;
    uint4 w4 = ((const uint4*)g_parbm)[b * 256u + t];
    unsigned wv[4] = { w4.x, w4.y, w4.z, w4.w };
    unsigned cnt = __popc(wv[0]) + __popc(wv[1]) + __popc(wv[2]) + __popc(wv[3]);
    unsigned lane = t & 31, wid = t >> 5;
    unsigned inc = cnt;
    #pragma unroll
    for (int d = 1; d < 32; d <<= 1) {
        unsigned u = __shfl_up_sync(0xffffffffu, inc, d);
        if (lane >= d) inc += u;
    }
    __shared__ unsigned ws[8];
    if (lane == 31) ws[wid] = inc;
    __syncthreads();
    if (t == 0) {
        unsigned s = 0;
        #pragma unroll
        for (int i = 0; i < 8; i++) { unsigned x = ws[i]; ws[i] = s; s += x; }
    }
    __syncthreads();
    unsigned r = g_boff[b] + ws[wid] + (inc - cnt);
    if (cnt == 0) return;
    #pragma unroll
    for (int q = 0; q < 4; q++) {
        unsigned w = wv[q];
        unsigned P0 = (widx0 + q) * 32u;
        while (w) {
            unsigned bitp = __ffs(w) - 1u;
            w &= w - 1u;
            if (r < PLIST_CAP) g_plist[r] = P0 + bitp;
            r++;
        }
    }
}

// ------ emit: coords at out[3i..), occ rows at out[3N+8i..), tail padded ----
__global__ void emit_kernel(float* __restrict__ out, int n, int vec4ok) {
    int i = blockIdx.x * blockDim.x + threadIdx.x;
    if (i >= n) return;
    unsigned np = g_total;
    float* crow = out + 3ull * (unsigned)i;
    float* orow = out + 3ull * (unsigned)n + 8ull * (unsigned)i;

    unsigned sp = 0, py = 0, pz = 0;
    bool valid = false;
    if ((unsigned)i < np) {
        unsigned P = g_plist[i];
        sp = P >> 18;                 // s' = s XOR 128 (ordered)
        py = (P >> 9) & 511u;
        pz = P & 511u;
        valid = (sp >= 128u);         // wrapped key >= 0  <=>  s < 128
    }
    if (!valid) {
        crow[0] = -1.0f; crow[1] = -1.0f; crow[2] = -1.0f;
        if (vec4ok) {
            float4 z4 = make_float4(0.f, 0.f, 0.f, 0.f);
            ((float4*)orow)[0] = z4;
            ((float4*)orow)[1] = z4;
        } else {
            #pragma unroll
            for (int c = 0; c < 8; c++) orow[c] = 0.0f;
        }
        return;
    }
    unsigned s = sp - 128u;           // valid px decode in [0,128)
    crow[0] = (float)s;
    crow[1] = (float)py;
    crow[2] = (float)pz;
    // folded child base: (2s)<<20 | (2py)<<10 | (2pz); 2s+i stays < 256
    unsigned cb = (s << 21) | (py << 11) | (pz << 1);
    unsigned e  = cb & 31u;           // even
    unsigned w00 = g_leafbm[cb >> 5];
    unsigned w01 = g_leafbm[(cb + (1u << 10)) >> 5];
    unsigned w10 = g_leafbm[(cb + (1u << 20)) >> 5];
    unsigned w11 = g_leafbm[(cb + (1u << 20) + (1u << 10)) >> 5];
    float o0 = (float)((w00 >> e) & 1u);        // (0,0,0)
    float o1 = (float)((w00 >> (e + 1)) & 1u);  // (0,0,1)
    float o2 = (float)((w01 >> e) & 1u);        // (0,1,0)
    float o3 = (float)((w01 >> (e + 1)) & 1u);  // (0,1,1)
    float o4 = (float)((w10 >> e) & 1u);        // (1,0,0)
    float o5 = (float)((w10 >> (e + 1)) & 1u);  // (1,0,1)
    float o6 = (float)((w11 >> e) & 1u);        // (1,1,0)
    float o7 = (float)((w11 >> (e + 1)) & 1u);  // (1,1,1)
    if (vec4ok) {
        ((float4*)orow)[0] = make_float4(o0, o1, o2, o3);
        ((float4*)orow)[1] = make_float4(o4, o5, o6, o7);
    } else {
        orow[0] = o0; orow[1] = o1; orow[2] = o2; orow[3] = o3;
        orow[4] = o4; orow[5] = o5; orow[6] = o6; orow[7] = o7;
    }
}

extern "C" void kernel_launch(void* const* d_in, const int* in_sizes, int n_in,
                              void* d_out, int out_size) {
    const float* leaf = (const float*)d_in[0];
    long long n = in_sizes[0] / 3;
    float* out = (float*)d_out;
    if (out_size < 11 * n) return;

    static void* lbm = nullptr;
    static void* pbm = nullptr;
    if (!lbm) {
        cudaGetSymbolAddress(&lbm, g_leafbm);
        cudaGetSymbolAddress(&pbm, g_parbm);
    }
    cudaMemsetAsync(lbm, 0, sizeof(g_leafbm));
    cudaMemsetAsync(pbm, 0, sizeof(g_parbm));

    int tb = 256;
    int nb = (int)((n + tb - 1) / tb);
    int vec4ok = ((n & 3) == 0) ? 1 : 0;   // occ base (3n) 16B-aligned
    scatter_kernel<<<nb, tb>>>(leaf, (int)n);
    blocksum_kernel<<<NBLK, 256>>>();
    scan_kernel<<<1, 512>>>();
    compact_kernel<<<NBLK, 256>>>();
    emit_kernel<<<nb, tb>>>(out, (int)n, vec4ok);
}

// round 14
// speedup vs baseline: 1.0669x; 1.0669x over previous
#include <cuda_runtime.h>
#include <cstdint>

// Octree parent occupancy replicating the reference AS-EXECUTED under JAX
// default int32 (key arithmetic wraps mod 2^32 = 256*2^24):
//   - parent key folds px -> s = px mod 256, signed rep s-256 for s>=128
//   - unique/sort over folded keys; valid = (wrapped key >= 0) <=> s < 128
//   - valid rows decode to (s, py, pz); invalid rows -> (-1,-1,-1), occ=0
//   - leaf keys fold x mod 256; child query matches x = 2s+i (mod 256)
// Ordered parent index: P' = (s XOR 128)<<18 | py<<9 | pz (ascending == ref order)
// Invalid parents occupy P' < 2^25 (lower bitmap half) and all emit the same
// constant row, so only their COUNT (n_neg) is needed — compact skips them.
// Output layout: [ parent_C: N x 3 floats | occupancy: N x 8 floats ]

#define LEAF_WORDS (1u << 23)   // 2^28 bits (x mod 256, y, z) = 32 MiB
#define PAR_WORDS  (1u << 21)   // 2^26 bits = 8 MiB
#define NBLK       2048
#define HALFBLK    1024         // blocks covering the valid (upper) half
#define WPB        1024         // NBLK*WPB == PAR_WORDS
#define PLIST_CAP  (1u << 22)

__device__ __align__(16) unsigned g_leafbm[LEAF_WORDS];
__device__ __align__(16) unsigned g_parbm[PAR_WORDS];
__device__ __align__(16) unsigned g_bsum[NBLK];
__device__ __align__(16) unsigned g_boff[NBLK];
__device__ __align__(16) unsigned g_plist[PLIST_CAP];
__device__ unsigned g_total;    // Np (unique folded keys, valid + invalid)
__device__ unsigned g_nneg;     // number of unique invalid (negative-fold) keys

// ---------------------------------------------------------------- scatter ---
__global__ void scatter_kernel(const float* __restrict__ leaf, int n) {
    int i = blockIdx.x * blockDim.x + threadIdx.x;
    if (i >= n) return;
    unsigned x = ((unsigned)(int)leaf[3 * i + 0]) & 1023u;
    unsigned y = ((unsigned)(int)leaf[3 * i + 1]) & 1023u;
    unsigned z = ((unsigned)(int)leaf[3 * i + 2]) & 1023u;
    unsigned L = ((x & 255u) << 20) | (y << 10) | z;      // folded leaf key
    atomicOr(&g_leafbm[L >> 5], 1u << (L & 31));
    unsigned s  = (x >> 1) & 255u;                        // px mod 256
    unsigned Pp = ((s ^ 128u) << 18) | ((y >> 1) << 9) | (z >> 1);
    atomicOr(&g_parbm[Pp >> 5], 1u << (Pp & 31));         // unconditional (fold!)
}

// --------------------------------------------------------- per-block sums ---
__global__ void blocksum_kernel() {
    unsigned t = threadIdx.x, b = blockIdx.x;
    const uint4* p = (const uint4*)g_parbm;
    uint4 w = p[(size_t)b * (WPB / 4) + t];
    unsigned c = __popc(w.x) + __popc(w.y) + __popc(w.z) + __popc(w.w);
    unsigned lane = t & 31, wid = t >> 5;
    #pragma unroll
    for (int d = 16; d; d >>= 1) c += __shfl_down_sync(0xffffffffu, c, d);
    __shared__ unsigned ws[8];
    if (lane == 0) ws[wid] = c;
    __syncthreads();
    if (t == 0) {
        unsigned s = 0;
        #pragma unroll
        for (int i = 0; i < 8; i++) s += ws[i];
        g_bsum[b] = s;
    }
}

// ------------------------------------------------ scan of 2048 block sums ---
__global__ void scan_kernel() {
    unsigned t = threadIdx.x;                       // 512 threads x 4 sums
    uint4 v = ((const uint4*)g_bsum)[t];
    unsigned s0 = v.x, s1 = v.y, s2 = v.z, s3 = v.w;
    unsigned tot = s0 + s1 + s2 + s3;
    unsigned lane = t & 31, wid = t >> 5;
    unsigned inc = tot;
    #pragma unroll
    for (int d = 1; d < 32; d <<= 1) {
        unsigned u = __shfl_up_sync(0xffffffffu, inc, d);
        if (lane >= d) inc += u;
    }
    __shared__ unsigned ws[16];
    if (lane == 31) ws[wid] = inc;
    __syncthreads();
    if (t == 0) {
        unsigned s = 0;
        #pragma unroll
        for (int i = 0; i < 16; i++) { unsigned x = ws[i]; ws[i] = s; s += x; }
        g_total = s;
    }
    __syncthreads();
    unsigned ex = ws[wid] + inc - tot;
    uint4 o;
    o.x = ex; o.y = ex + s0; o.z = ex + s0 + s1; o.w = ex + s0 + s1 + s2;
    ((uint4*)g_boff)[t] = o;
    if (t == HALFBLK / 4) g_nneg = o.x;   // exclusive prefix at block 1024
}

// ------------- ordered compaction, VALID (upper) half only -----------------
__global__ void compact_kernel() {
    unsigned t = threadIdx.x;
    unsigned b = blockIdx.x + HALFBLK;              // upper-half parbm blocks
    unsigned widx0 = (b * 256u + t) * 4u;
    uint4 w4 = ((const uint4*)g_parbm)[b * 256u + t];
    unsigned wv[4] = { w4.x, w4.y, w4.z, w4.w };
    unsigned cnt = __popc(wv[0]) + __popc(wv[1]) + __popc(wv[2]) + __popc(wv[3]);
    unsigned lane = t & 31, wid = t >> 5;
    unsigned inc = cnt;
    #pragma unroll
    for (int d = 1; d < 32; d <<= 1) {
        unsigned u = __shfl_up_sync(0xffffffffu, inc, d);
        if (lane >= d) inc += u;
    }
    __shared__ unsigned ws[8];
    if (lane == 31) ws[wid] = inc;
    __syncthreads();
    if (t == 0) {
        unsigned s = 0;
        #pragma unroll
        for (int i = 0; i < 8; i++) { unsigned x = ws[i]; ws[i] = s; s += x; }
    }
    __syncthreads();
    unsigned r = g_boff[b] + ws[wid] + (inc - cnt);
    if (cnt == 0) return;
    #pragma unroll
    for (int q = 0; q < 4; q++) {
        unsigned w = wv[q];
        unsigned P0 = (widx0 + q) * 32u;
        while (w) {
            unsigned bitp = __ffs(w) - 1u;
            w &= w - 1u;
            if (r < PLIST_CAP) g_plist[r] = P0 + bitp;
            r++;
        }
    }
}

// ------ emit: coords at out[3i..), occ rows at out[3N+8i..) ----------------
// rows [0,n_neg) and [np,n): constant fill; rows [n_neg,np): real parents.
__global__ void emit_kernel(float* __restrict__ out, int n, int vec4ok) {
    int i = blockIdx.x * blockDim.x + threadIdx.x;
    if (i >= n) return;
    unsigned np = g_total;
    unsigned nneg = g_nneg;
    float* crow = out + 3ull * (unsigned)i;
    float* orow = out + 3ull * (unsigned)n + 8ull * (unsigned)i;

    if ((unsigned)i < nneg || (unsigned)i >= np) {  // invalid parent or pad
        crow[0] = -1.0f; crow[1] = -1.0f; crow[2] = -1.0f;
        if (vec4ok) {
            float4 z4 = make_float4(0.f, 0.f, 0.f, 0.f);
            ((float4*)orow)[0] = z4;
            ((float4*)orow)[1] = z4;
        } else {
            #pragma unroll
            for (int c = 0; c < 8; c++) orow[c] = 0.0f;
        }
        return;
    }
    unsigned P  = g_plist[i];
    unsigned s  = (P >> 18) - 128u;   // valid px decode in [0,128)
    unsigned py = (P >> 9) & 511u;
    unsigned pz = P & 511u;
    crow[0] = (float)s;
    crow[1] = (float)py;
    crow[2] = (float)pz;
    // folded child base: (2s)<<20 | (2py)<<10 | (2pz); 2s+i stays < 256
    unsigned cb = (s << 21) | (py << 11) | (pz << 1);
    unsigned e  = cb & 31u;           // even
    unsigned w00 = g_leafbm[cb >> 5];
    unsigned w01 = g_leafbm[(cb + (1u << 10)) >> 5];
    unsigned w10 = g_leafbm[(cb + (1u << 20)) >> 5];
    unsigned w11 = g_leafbm[(cb + (1u << 20) + (1u << 10)) >> 5];
    float o0 = (float)((w00 >> e) & 1u);        // (0,0,0)
    float o1 = (float)((w00 >> (e + 1)) & 1u);  // (0,0,1)
    float o2 = (float)((w01 >> e) & 1u);        // (0,1,0)
    float o3 = (float)((w01 >> (e + 1)) & 1u);  // (0,1,1)
    float o4 = (float)((w10 >> e) & 1u);        // (1,0,0)
    float o5 = (float)((w10 >> (e + 1)) & 1u);  // (1,0,1)
    float o6 = (float)((w11 >> e) & 1u);        // (1,1,0)
    float o7 = (float)((w11 >> (e + 1)) & 1u);  // (1,1,1)
    if (vec4ok) {
        ((float4*)orow)[0] = make_float4(o0, o1, o2, o3);
        ((float4*)orow)[1] = make_float4(o4, o5, o6, o7);
    } else {
        orow[0] = o0; orow[1] = o1; orow[2] = o2; orow[3] = o3;
        orow[4] = o4; orow[5] = o5; orow[6] = o6; orow[7] = o7;
    }
}

extern "C" void kernel_launch(void* const* d_in, const int* in_sizes, int n_in,
                              void* d_out, int out_size) {
    const float* leaf = (const float*)d_in[0];
    long long n = in_sizes[0] / 3;
    float* out = (float*)d_out;
    if (out_size < 11 * n) return;

    static void* lbm = nullptr;
    static void* pbm = nullptr;
    if (!lbm) {
        cudaGetSymbolAddress(&lbm, g_leafbm);
        cudaGetSymbolAddress(&pbm, g_parbm);
    }
    cudaMemsetAsync(lbm, 0, sizeof(g_leafbm));
    cudaMemsetAsync(pbm, 0, sizeof(g_parbm));

    int tb = 256;
    int nb = (int)((n + tb - 1) / tb);
    int vec4ok = ((n & 3) == 0) ? 1 : 0;   // occ base (3n) 16B-aligned
    scatter_kernel<<<nb, tb>>>(leaf, (int)n);
    blocksum_kernel<<<NBLK, 256>>>();
    scan_kernel<<<1, 512>>>();
    compact_kernel<<<HALFBLK, 256>>>();
    emit_kernel<<<nb, tb>>>(out, (int)n, vec4ok);
}